// round 6
// baseline (speedup 1.0000x reference)
#include <cuda_runtime.h>
#include <cstdint>

#define FULLMASK 0xffffffffu

constexpr int D        = 128;   // embedding dim
constexpr int K        = 64;    // categorical dim
constexpr int BM       = 64;    // batch rows per block
constexpr int NTHREADS = 256;
constexpr int NNEG     = 5;
constexpr int MAXBLOCKS = 4096;

// device-global scratch (no allocs allowed)
__device__ float        g_WT[D * K];        // W transposed: [d][k], 32KB (L1-hot)
__device__ float        g_partials[MAXBLOCKS];
__device__ unsigned int g_counter = 0;

// dynamic smem: sPW [d][b][2] (prod, w_e) pairs = 64KB; phase-3 overlays sQ/sP.
constexpr int SPW_FLOATS = D * BM * 2;               // 16384
constexpr int SMEM_BYTES = SPW_FLOATS * 4;           // 65536 -> 3 blocks/SM

// ---------------- packed f32x2 helpers (PTX-only on Blackwell) ----------------
__device__ __forceinline__ unsigned long long fma2(unsigned long long a,
                                                   unsigned long long b,
                                                   unsigned long long c) {
    unsigned long long r;
    asm("fma.rn.f32x2 %0, %1, %2, %3;" : "=l"(r) : "l"(a), "l"(b), "l"(c));
    return r;
}
__device__ __forceinline__ unsigned long long dup2(float x) {
    unsigned long long r;
    asm("mov.b64 %0, {%1, %2};" : "=l"(r) : "f"(x), "f"(x));
    return r;
}
__device__ __forceinline__ float2 unpk(unsigned long long v) {
    float2 f;
    asm("mov.b64 {%0, %1}, %2;" : "=f"(f.x), "=f"(f.y) : "l"(v));
    return f;
}

__device__ __forceinline__ float wsum(float v) {
    #pragma unroll
    for (int o = 16; o > 0; o >>= 1) v += __shfl_xor_sync(FULLMASK, v, o);
    return v;
}
__device__ __forceinline__ float wmax(float v) {
    #pragma unroll
    for (int o = 16; o > 0; o >>= 1) v = fmaxf(v, __shfl_xor_sync(FULLMASK, v, o));
    return v;
}
__device__ __forceinline__ float dot4(float4 a, float4 b) {
    return fmaf(a.x, b.x, fmaf(a.y, b.y, fmaf(a.z, b.z, a.w * b.w)));
}
__device__ __forceinline__ float log_sigmoid(float x) {
    float e = __expf(-fabsf(x));
    return fminf(x, 0.0f) - __logf(1.0f + e);
}

// =============================================================================
// Tiny one-time kernel: transpose community_w into g_WT[d][k]
// =============================================================================
__global__ void gcn_wt_setup(const float* __restrict__ Wg)
{
    int i = blockIdx.x * blockDim.x + threadIdx.x;   // 2048 float4s
    if (i >= K * D / 4) return;
    float4 v = ((const float4*)Wg)[i];
    int k  = i >> 5;            // row of community_w (D/4 = 32 float4 per row)
    int d0 = (i & 31) << 2;
    g_WT[(d0 + 0) * K + k] = v.x;
    g_WT[(d0 + 1) * K + k] = v.y;
    g_WT[(d0 + 2) * K + k] = v.z;
    g_WT[(d0 + 3) * K + k] = v.w;
}

// =============================================================================
// Fused kernel.
// GEMM tiling: warps 0-3 compute k[0..32), warps 4-7 compute k[32..64).
// Within a warp: lane&3 -> 8-wide k-group; lane>>2 -> row-pair (2 rows).
// Per warp per d: 128B of W (1 wf) + 128B of A pairs (1 wf), 3 LSU instrs/thread.
// =============================================================================
__global__ __launch_bounds__(NTHREADS, 3)
void gcn_gumbel_mega(const int*   __restrict__ widx,
                     const int*   __restrict__ cidx,
                     const int*   __restrict__ negidx,
                     const float* __restrict__ gumbel,
                     const float* __restrict__ node_emb,
                     const float* __restrict__ ctx_emb,
                     const float* __restrict__ Wg,       // community_w [K][D]
                     float*       __restrict__ out0,     // loss scalar
                     float*       __restrict__ outq,     // softmax(q)  [B][K]
                     float*       __restrict__ outp,     // prior       [B][K]
                     int Btot, float invB)
{
    extern __shared__ float smem[];
    float* sPW = smem;                 // [d][b][2] (prod, w_e)

    __shared__ float sred[8];
    __shared__ int   s_last;

    const int tid  = threadIdx.x;
    const int lane = tid & 31;
    const int warp = tid >> 5;
    const int b0   = blockIdx.x * BM;

    // ---------------- Phase 1: embedding gathers -> smem pairs ----------------
    {
        int r       = tid >> 2;        // 0..63 local row
        int quarter = tid & 3;         // 0..3
        int b       = min(b0 + r, Btot - 1);
        int wi = widx[b];
        int ci = cidx[b];
        const float4* wp = (const float4*)(node_emb + (size_t)wi * D + quarter * 32);
        const float4* cp = (const float4*)(node_emb + (size_t)ci * D + quarter * 32);
        float2* dst = (float2*)sPW;    // pair index = d*BM + r
        #pragma unroll
        for (int j = 0; j < 8; j++) {
            float4 a  = wp[j];
            float4 bb = cp[j];
            int dbase = quarter * 32 + j * 4;
            dst[(dbase + 0) * BM + r] = make_float2(a.x * bb.x, a.x);
            dst[(dbase + 1) * BM + r] = make_float2(a.y * bb.y, a.y);
            dst[(dbase + 2) * BM + r] = make_float2(a.z * bb.z, a.z);
            dst[(dbase + 3) * BM + r] = make_float2(a.w * bb.w, a.w);
        }
    }
    __syncthreads();

    // ---------------- Phase 2: dual GEMM, k split across warp halves ----------
    const int kb = (warp >= 4 ? 32 : 0) + (lane & 3) * 8;      // 8 k per thread
    const int rb = ((warp & 3) * 8 + (lane >> 2)) * 2;         // 2 rows per thread

    unsigned long long acc[2][8];
    #pragma unroll
    for (int i = 0; i < 2; i++)
        #pragma unroll
        for (int j = 0; j < 8; j++) acc[i][j] = 0ull;

    #pragma unroll 4
    for (int d = 0; d < D; d++) {
        const float4* Wrow = (const float4*)(g_WT + (size_t)d * K + kb);
        float4 wa = __ldg(Wrow);
        float4 wb = __ldg(Wrow + 1);
        // A pairs for 2 adjacent rows: one 16B LDS
        const unsigned long long* pw =
            (const unsigned long long*)(sPW + (size_t)(d * BM + rb) * 2);
        unsigned long long a0 = pw[0];
        unsigned long long a1 = pw[1];

        unsigned long long w0 = dup2(wa.x), w1 = dup2(wa.y);
        unsigned long long w2 = dup2(wa.z), w3 = dup2(wa.w);
        unsigned long long w4 = dup2(wb.x), w5 = dup2(wb.y);
        unsigned long long w6 = dup2(wb.z), w7 = dup2(wb.w);

        acc[0][0] = fma2(a0, w0, acc[0][0]);
        acc[0][1] = fma2(a0, w1, acc[0][1]);
        acc[0][2] = fma2(a0, w2, acc[0][2]);
        acc[0][3] = fma2(a0, w3, acc[0][3]);
        acc[0][4] = fma2(a0, w4, acc[0][4]);
        acc[0][5] = fma2(a0, w5, acc[0][5]);
        acc[0][6] = fma2(a0, w6, acc[0][6]);
        acc[0][7] = fma2(a0, w7, acc[0][7]);
        acc[1][0] = fma2(a1, w0, acc[1][0]);
        acc[1][1] = fma2(a1, w1, acc[1][1]);
        acc[1][2] = fma2(a1, w2, acc[1][2]);
        acc[1][3] = fma2(a1, w3, acc[1][3]);
        acc[1][4] = fma2(a1, w4, acc[1][4]);
        acc[1][5] = fma2(a1, w5, acc[1][5]);
        acc[1][6] = fma2(a1, w6, acc[1][6]);
        acc[1][7] = fma2(a1, w7, acc[1][7]);
    }
    __syncthreads();   // all phase-2 reads of sPW done before overlay

    // ---------------- Phase 3: dump q / prior logits (vectorized) -------------
    float* sQ = smem;            // [BM][K] = 16KB
    float* sP = smem + BM * K;   // [BM][K] = 16KB
    #pragma unroll
    for (int i = 0; i < 2; i++) {
        float2 t0 = unpk(acc[i][0]);
        float2 t1 = unpk(acc[i][1]);
        float2 t2 = unpk(acc[i][2]);
        float2 t3 = unpk(acc[i][3]);
        float2 t4 = unpk(acc[i][4]);
        float2 t5 = unpk(acc[i][5]);
        float2 t6 = unpk(acc[i][6]);
        float2 t7 = unpk(acc[i][7]);
        *(float4*)&sQ[(rb + i) * K + kb]     = make_float4(t0.x, t1.x, t2.x, t3.x);
        *(float4*)&sQ[(rb + i) * K + kb + 4] = make_float4(t4.x, t5.x, t6.x, t7.x);
        *(float4*)&sP[(rb + i) * K + kb]     = make_float4(t0.y, t1.y, t2.y, t3.y);
        *(float4*)&sP[(rb + i) * K + kb + 4] = make_float4(t4.y, t5.y, t6.y, t7.y);
    }
    __syncthreads();

    // ---------------- Phase 4+5: per-warp rows (no cross-warp sync) -----------
    float lacc = 0.0f;
    #pragma unroll 2
    for (int j = 0; j < 8; j++) {
        int r = warp * 8 + j;
        int b = b0 + r;
        if (b >= Btot) break;

        // ---- issue ALL independent loads first (latency overlap) ----
        int ci = cidx[b];
        int n0 = negidx[(size_t)b * NNEG + 0];
        int n1 = negidx[(size_t)b * NNEG + 1];
        int n2 = negidx[(size_t)b * NNEG + 2];
        int n3 = negidx[(size_t)b * NNEG + 3];
        int n4 = negidx[(size_t)b * NNEG + 4];
        float4 cv = *(const float4*)(ctx_emb + (size_t)ci * D + (lane << 2));
        float4 v0 = *(const float4*)(ctx_emb + (size_t)n0 * D + (lane << 2));
        float4 v1 = *(const float4*)(ctx_emb + (size_t)n1 * D + (lane << 2));
        float4 v2 = *(const float4*)(ctx_emb + (size_t)n2 * D + (lane << 2));
        float4 v3 = *(const float4*)(ctx_emb + (size_t)n3 * D + (lane << 2));
        float4 v4 = *(const float4*)(ctx_emb + (size_t)n4 * D + (lane << 2));
        float g1 = __ldcs(gumbel + (size_t)b * K + lane);
        float g2 = __ldcs(gumbel + (size_t)b * K + 32 + lane);
        float q1 = sQ[r * K + lane];
        float q2 = sQ[r * K + 32 + lane];
        float p1 = sP[r * K + lane];
        float p2 = sP[r * K + 32 + lane];

        // ---- argmax(q + gumbel) first, so the W[k*] gather can fly early ----
        float av = q1 + g1;
        int   ai = lane;
        {
            float a2v = q2 + g2;
            if (a2v > av) { av = a2v; ai = lane + 32; }
        }
        float    mv  = wmax(av);
        unsigned msk = __ballot_sync(FULLMASK, av == mv);
        int      kst = __shfl_sync(FULLMASK, ai, __ffs(msk) - 1);
        float4 wv = *(const float4*)(Wg + (size_t)kst * D + (lane << 2));

        // ---- softmax(q) ----
        float mq  = wmax(fmaxf(q1, q2));
        float e1  = __expf(q1 - mq);
        float e2  = __expf(q2 - mq);
        float inv = __fdividef(1.0f, wsum(e1 + e2));
        __stcs(outq + (size_t)b * K + lane,      e1 * inv);
        __stcs(outq + (size_t)b * K + 32 + lane, e2 * inv);

        // ---- softmax(prior) ----
        float mp = wmax(fmaxf(p1, p2));
        float f1 = __expf(p1 - mp);
        float f2 = __expf(p2 - mp);
        float ip = __fdividef(1.0f, wsum(f1 + f2));
        __stcs(outp + (size_t)b * K + lane,      f1 * ip);
        __stcs(outp + (size_t)b * K + 32 + lane, f2 * ip);

        // ---- loss dots ----
        float s0 = dot4(wv, cv);
        float s1 = dot4(wv, v0);
        float s2 = dot4(wv, v1);
        float s3 = dot4(wv, v2);
        float s4 = dot4(wv, v3);
        float s5 = dot4(wv, v4);
        s0 = wsum(s0); s1 = wsum(s1); s2 = wsum(s2);
        s3 = wsum(s3); s4 = wsum(s4); s5 = wsum(s5);

        float term = log_sigmoid(s0);
        float nsum = log_sigmoid(-s1) + log_sigmoid(-s2) + log_sigmoid(-s3)
                   + log_sigmoid(-s4) + log_sigmoid(-s5);
        term = fmaf(nsum, 1.0f / (float)NNEG, term);
        if (lane == 0) lacc += term;
    }

    // ---------------- Block partial + last-block deterministic reduce ---------
    if (lane == 0) sred[warp] = lacc;
    __syncthreads();
    if (tid == 0) {
        float s = 0.0f;
        #pragma unroll
        for (int i = 0; i < 8; i++) s += sred[i];
        g_partials[blockIdx.x] = s;
        __threadfence();
        unsigned t = atomicAdd(&g_counter, 1u);
        s_last = (t == gridDim.x - 1) ? 1 : 0;
    }
    __syncthreads();

    if (s_last) {
        float s = 0.0f;
        for (int i = tid; i < (int)gridDim.x; i += NTHREADS)
            s += __ldcg(&g_partials[i]);
        smem[tid] = s;
        __syncthreads();
        #pragma unroll
        for (int o = NTHREADS / 2; o > 0; o >>= 1) {
            if (tid < o) smem[tid] += smem[tid + o];
            __syncthreads();
        }
        if (tid == 0) {
            out0[0] = -smem[0] * invB;
            g_counter = 0;   // reset for next (graph-replayed) launch
        }
    }
}

// =============================================================================
extern "C" void kernel_launch(void* const* d_in, const int* in_sizes, int n_in,
                              void* d_out, int out_size)
{
    const int*   w        = (const int*)  d_in[0];
    const int*   c        = (const int*)  d_in[1];
    const int*   neg      = (const int*)  d_in[2];
    // d_in[3] = temp (==1): only rescales the argmax input -> provably irrelevant
    const float* gumbel   = (const float*)d_in[4];
    const float* node_emb = (const float*)d_in[5];
    const float* ctx_emb  = (const float*)d_in[6];
    const float* Wg       = (const float*)d_in[7];

    const int B = in_sizes[0];

    float* out       = (float*)d_out;
    float* out_q     = out + 1;
    float* out_prior = out + 1 + (size_t)B * K;

    int nb = (B + BM - 1) / BM;     // 2048 for B=131072
    if (nb > MAXBLOCKS) nb = MAXBLOCKS;

    cudaFuncSetAttribute(gcn_gumbel_mega,
                         cudaFuncAttributeMaxDynamicSharedMemorySize, SMEM_BYTES);

    gcn_wt_setup<<<(K * D / 4 + 255) / 256, 256>>>(Wg);
    gcn_gumbel_mega<<<nb, NTHREADS, SMEM_BYTES>>>(
        w, c, neg, gumbel, node_emb, ctx_emb, Wg,
        out, out_q, out_prior, B, 1.0f / (float)B);
}